// round 13
// baseline (speedup 1.0000x reference)
#include <cuda_runtime.h>
#include <cstdint>

// Blocked Hadamard transform, BLOCK = 256 = 4^4.
// H4 = ones(4) - 2*antidiag ; H = kron(H4 x4) / 16.
// In-block index i = i0 + 4*i1 + 16*i2 + 64*i3 (base-4 digits).
//
// Persistent grid-stride version of the R9 layout. Warp tile = 512 consecutive
// floats (2 blocks), 4 float4 chunks per thread:
//   idx = 4*lane + e + 128*c,  e in [0,4), c in [0,4)
//   -> i0 = e (register-local), i1 = lane[1:0], i2 = lane[3:2],
//      i3 = (c&1)<<1 | lane[4], block = c>>1.
// All global accesses are warp-contiguous LDG.128/STG.128 (512B per inst).
// Grid-stride loop: iterations are independent, so iteration k+1's loads
// overlap iteration k's stores (cross-iteration MLP at zero register cost),
// and there are no wave transitions / tail waves.
//
// Per-thread stage costs per tile: i0 free (fused into load), i3 split-digit
// butterfly (8 SHFL), i1/i2 two-shuffle identity (32 each): 72 SHFL.

__global__ void __launch_bounds__(256) hadamard256_kernel(
    const float* __restrict__ x, float* __restrict__ out,
    unsigned n_tiles)   // total 512-float warp tiles
{
    const unsigned nwarps = gridDim.x * 8u;
    const unsigned warp0  = blockIdx.x * 8u + (threadIdx.x >> 5);
    const unsigned lane   = threadIdx.x & 31u;

    for (unsigned w = warp0; w < n_tiles; w += nwarps) {
        const size_t base4 = (size_t)w * 128u + lane;
        const float4* xp = reinterpret_cast<const float4*>(x) + base4;

        float4 v[4];
        #pragma unroll
        for (int c = 0; c < 4; c++) {
            float4 t = __ldcs(xp + 32 * c);
            // ---- Stage i0 (register-local H4 within the float4) ----
            float s01 = t.x + t.y, d01 = t.x - t.y;
            float s23 = t.z + t.w, d23 = t.z - t.w;
            v[c].x = s01 + d23;   //  x0+x1+x2-x3
            v[c].y = s01 - d23;   //  x0+x1-x2+x3
            v[c].z = d01 + s23;   //  x0-x1+x2+x3
            v[c].w = s23 - d01;   // -x0+x1+x2+x3
        }

        // ---- Stage i3: split digit (low bit = lane bit 4, high bit = c bit 0).
        // Pairs (c=0,c=1) and (c=2,c=3); ONE shuffle per element pair:
        //   s = A+B; d = A-B; ds = shfl_xor(d,16); A' = s+ds; B' = s-ds
        #pragma unroll
        for (int p = 0; p < 2; p++) {
            float* A = reinterpret_cast<float*>(&v[2 * p]);
            float* B = reinterpret_cast<float*>(&v[2 * p + 1]);
            #pragma unroll
            for (int e = 0; e < 4; e++) {
                float s = A[e] + B[e];
                float d = A[e] - B[e];
                float ds = __shfl_xor_sync(0xffffffffu, d, 16);
                A[e] = s + ds;
                B[e] = s - ds;
            }
        }

        // ---- Stage i1: lane bits [1:0], 2-shuffle identity ----
        {
            float* f = reinterpret_cast<float*>(v);
            #pragma unroll
            for (int j = 0; j < 16; j++) {
                float a  = __shfl_xor_sync(0xffffffffu, f[j], 1);
                float s  = f[j] + a;
                float d  = f[j] - a;
                float d2 = __shfl_xor_sync(0xffffffffu, d, 2);
                f[j] = s + d2;
            }
        }

        // ---- Stage i2: lane bits [3:2], 2-shuffle identity, fold 1/16 ----
        {
            float* f = reinterpret_cast<float*>(v);
            #pragma unroll
            for (int j = 0; j < 16; j++) {
                float a  = __shfl_xor_sync(0xffffffffu, f[j], 4);
                float s  = f[j] + a;
                float d  = f[j] - a;
                float d2 = __shfl_xor_sync(0xffffffffu, d, 8);
                f[j] = (s + d2) * 0.0625f;
            }
        }

        float4* op = reinterpret_cast<float4*>(out) + base4;
        #pragma unroll
        for (int c = 0; c < 4; c++)
            __stcs(op + 32 * c, v[c]);
    }
}

extern "C" void kernel_launch(void* const* d_in, const int* in_sizes, int n_in,
                              void* d_out, int out_size)
{
    const float* x = (const float*)d_in[0];
    float* out = (float*)d_out;

    // out_size = 2*4096*8192 = 67,108,864 floats -> 131072 warp tiles of 512.
    const unsigned n_tiles = (unsigned)((long long)out_size / 512);

    // Persistent launch: 8 CTAs per SM (32 regs/thread, 256 thr -> occ 8).
    // GB300 has 152 SMs; 152*8 = 1216 CTAs, each warp loops ~13.5 tiles.
    const int grid = 1216;

    hadamard256_kernel<<<grid, 256>>>(x, out, n_tiles);
}

// round 14
// speedup vs baseline: 1.1024x; 1.1024x over previous
#include <cuda_runtime.h>
#include <cstdint>

// Blocked Hadamard transform, BLOCK = 256 = 4^4.
// H4 = ones(4) - 2*antidiag ; H = kron(H4 x4) / 16.
// In-block index i = i0 + 4*i1 + 16*i2 + 64*i3 (base-4 digits).
//
// R9 layout (best measured). Warp handles 512 consecutive floats (2 blocks)
// as 4 float4 chunks per thread:
//   idx = 4*lane + e + 128*c,  e in [0,4), c in [0,4)
//   -> i0 = e (register-local), i1 = lane[1:0], i2 = lane[3:2],
//      i3 = (c&1)<<1 | lane[4], block = c>>1.
// All global accesses are warp-contiguous LDG.128/STG.128 (512B per inst).
//
// Change vs R9: after stage i3, stages i1/i2 are per-value independent, so
// they are executed PER CHUNK with the chunk's STG.128 issued immediately —
// stores start after ~1/4 of the shuffle work instead of all of it, and the
// write stream overlaps the remaining shuffles.
//
// Per-thread shuffles: i3 split-digit butterfly (8), i1/i2 two-shuffle
// identity (32 each) = 72 total.

__global__ void __launch_bounds__(256) hadamard256_kernel(
    const float* __restrict__ x, float* __restrict__ out)
{
    const unsigned warp_global = blockIdx.x * 8u + (threadIdx.x >> 5);
    const unsigned lane = threadIdx.x & 31u;
    // base in float4 units; warp accesses are contiguous 512B per instruction
    const size_t base4 = (size_t)warp_global * 128u + lane;

    const float4* xp = reinterpret_cast<const float4*>(x) + base4;
    float4* op = reinterpret_cast<float4*>(out) + base4;

    float4 v[4];
    #pragma unroll
    for (int c = 0; c < 4; c++) {
        float4 t = __ldcs(xp + 32 * c);
        // ---- Stage i0 (register-local H4 within the float4) ----
        float s01 = t.x + t.y, d01 = t.x - t.y;
        float s23 = t.z + t.w, d23 = t.z - t.w;
        v[c].x = s01 + d23;   //  x0+x1+x2-x3
        v[c].y = s01 - d23;   //  x0+x1-x2+x3
        v[c].z = d01 + s23;   //  x0-x1+x2+x3
        v[c].w = s23 - d01;   // -x0+x1+x2+x3
    }

    // ---- Stage i3: split digit (low bit = lane bit 4, high bit = c bit 0).
    // Pairs (c=0,c=1) and (c=2,c=3); ONE shuffle per element pair:
    //   s = A+B; d = A-B; ds = shfl_xor(d,16); A' = s+ds; B' = s-ds
    #pragma unroll
    for (int p = 0; p < 2; p++) {
        float* A = reinterpret_cast<float*>(&v[2 * p]);
        float* B = reinterpret_cast<float*>(&v[2 * p + 1]);
        #pragma unroll
        for (int e = 0; e < 4; e++) {
            float s = A[e] + B[e];
            float d = A[e] - B[e];
            float ds = __shfl_xor_sync(0xffffffffu, d, 16);
            A[e] = s + ds;
            B[e] = s - ds;
        }
    }

    // ---- Stages i1 + i2 per chunk, store immediately ----
    #pragma unroll
    for (int c = 0; c < 4; c++) {
        float* f = reinterpret_cast<float*>(&v[c]);
        // i1: lane bits [1:0], 2-shuffle identity
        #pragma unroll
        for (int e = 0; e < 4; e++) {
            float a  = __shfl_xor_sync(0xffffffffu, f[e], 1);
            float s  = f[e] + a;
            float d  = f[e] - a;
            float d2 = __shfl_xor_sync(0xffffffffu, d, 2);
            f[e] = s + d2;
        }
        // i2: lane bits [3:2], 2-shuffle identity, fold 1/16
        #pragma unroll
        for (int e = 0; e < 4; e++) {
            float a  = __shfl_xor_sync(0xffffffffu, f[e], 4);
            float s  = f[e] + a;
            float d  = f[e] - a;
            float d2 = __shfl_xor_sync(0xffffffffu, d, 8);
            f[e] = (s + d2) * 0.0625f;
        }
        __stcs(op + 32 * c, v[c]);
    }
}

extern "C" void kernel_launch(void* const* d_in, const int* in_sizes, int n_in,
                              void* d_out, int out_size)
{
    const float* x = (const float*)d_in[0];
    float* out = (float*)d_out;

    // out_size = 2*4096*8192 = 67,108,864 floats.
    // One warp handles 512 floats; 8 warps (256 threads) per CTA -> 4096 floats/CTA.
    const long long n = (long long)out_size;
    const int cta_elems = 4096;
    const int grid = (int)(n / cta_elems);   // 16384, exact

    hadamard256_kernel<<<grid, 256>>>(x, out);
}